// round 11
// baseline (speedup 1.0000x reference)
#include <cuda_runtime.h>
#include <math.h>

// ---------------- static scratch (no allocations allowed) ----------------
__device__ float g_conv[(size_t)800 * 84 * 84 * 64];   // conv output scratch (max layer)
__device__ float g_p1[(size_t)800 * 42 * 42 * 64];
__device__ float g_p2[(size_t)800 * 21 * 21 * 64];
__device__ float g_p3[(size_t)800 * 10 * 10 * 64];
__device__ float g_emb[(size_t)800 * 1600];
__device__ float g_xw[(size_t)2 * 800 * 128];
__device__ float g_spart[64 * 25 * 64 * 2];            // per-block stats partials
__device__ float g_stats[25 * 64 * 2];
__device__ float g_outs[(size_t)5 * 21 * 32 * 64];

__device__ __forceinline__ float sigf(float x) { return 1.f / (1.f + expf(-x)); }

typedef unsigned long long u64;

// broadcast one float into both lanes of a packed f32x2
__device__ __forceinline__ u64 pack_dup(float x) {
    u64 r;
    asm("mov.b64 %0, {%1, %1};" : "=l"(r) : "f"(x));
    return r;
}
__device__ __forceinline__ u64 pack2(float lo, float hi) {
    u64 r;
    asm("mov.b64 %0, {%1, %2};" : "=l"(r) : "f"(lo), "f"(hi));
    return r;
}
// d = a * b + d, two independent fp32 lanes (SASS FFMA2)
__device__ __forceinline__ void fma2(u64& d, u64 a, u64 b) {
    asm("fma.rn.f32x2 %0, %1, %2, %0;" : "+l"(d) : "l"(a), "l"(b));
}

// ---------------- conv1: 3->64, 84x84 SAME ----------------
// grid (21 strips, 800 imgs), 256 threads. Strip = 4 output rows.
__global__ void __launch_bounds__(256, 4)
k_conv1(const float* __restrict__ xs, const float* __restrict__ xq,
        const float* __restrict__ w, const float* __restrict__ bias) {
    __shared__ float s_in[6 * 86 * 3];
    __shared__ float s_w[27 * 64];
    const int tid = threadIdx.x;
    const int im = blockIdx.y;
    const int strip = blockIdx.x;
    const int g = im >> 5, n = im & 31;
    const float* src = (g < 20) ? xs + (size_t)(n * 20 + g) * (84 * 84 * 3)
                                : xq + (size_t)(n * 5 + (g - 20)) * (84 * 84 * 3);

    for (int i = tid; i < 27 * 64; i += 256) s_w[i] = w[i];
    for (int i = tid; i < 6 * 86 * 3; i += 256) {
        int ci = i % 3; int c = (i / 3) % 86; int r = i / (3 * 86);
        int gy = strip * 4 - 1 + r, gx = c - 1;
        float v = 0.f;
        if (gy >= 0 && gy < 84 && gx >= 0 && gx < 84) v = src[(gy * 84 + gx) * 3 + ci];
        s_in[i] = v;
    }
    __syncthreads();

    const int cg = tid & 3;    // cout group of 16 (= 8 pairs)
    const int ppb = tid >> 2;  // pixel-pair base 0..63
    u64 b2[8];
#pragma unroll
    for (int jp = 0; jp < 8; ++jp)
        b2[jp] = pack2(bias[cg * 16 + 2 * jp], bias[cg * 16 + 2 * jp + 1]);

    for (int it = 0; it < 3; ++it) {
        int pp = ppb + it * 64;
        if (pp < 168) {
            int prow = pp / 42;
            int col0 = (pp % 42) * 2;
            u64 acc0[8], acc1[8];
#pragma unroll
            for (int jp = 0; jp < 8; ++jp) { acc0[jp] = b2[jp]; acc1[jp] = b2[jp]; }
#pragma unroll
            for (int k = 0; k < 27; ++k) {
                int ky = k / 9, kx = (k % 9) / 3, ci = k % 3;
                u64 a0 = pack_dup(s_in[((prow + ky) * 86 + (col0 + kx)) * 3 + ci]);
                u64 a1 = pack_dup(s_in[((prow + ky) * 86 + (col0 + 1 + kx)) * 3 + ci]);
                const ulonglong2* wp = (const ulonglong2*)&s_w[k * 64 + cg * 16];
                ulonglong2 wA = wp[0], wB = wp[1], wC = wp[2], wD = wp[3];
                fma2(acc0[0], a0, wA.x); fma2(acc1[0], a1, wA.x);
                fma2(acc0[1], a0, wA.y); fma2(acc1[1], a1, wA.y);
                fma2(acc0[2], a0, wB.x); fma2(acc1[2], a1, wB.x);
                fma2(acc0[3], a0, wB.y); fma2(acc1[3], a1, wB.y);
                fma2(acc0[4], a0, wC.x); fma2(acc1[4], a1, wC.x);
                fma2(acc0[5], a0, wC.y); fma2(acc1[5], a1, wC.y);
                fma2(acc0[6], a0, wD.x); fma2(acc1[6], a1, wD.x);
                fma2(acc0[7], a0, wD.y); fma2(acc1[7], a1, wD.y);
            }
            int oy = strip * 4 + prow;
            size_t base = ((size_t)im * 7056 + (size_t)oy * 84 + col0) * 64 + cg * 16;
            ulonglong2* o0 = (ulonglong2*)&g_conv[base];
            o0[0] = make_ulonglong2(acc0[0], acc0[1]);
            o0[1] = make_ulonglong2(acc0[2], acc0[3]);
            o0[2] = make_ulonglong2(acc0[4], acc0[5]);
            o0[3] = make_ulonglong2(acc0[6], acc0[7]);
            ulonglong2* o1 = (ulonglong2*)&g_conv[base + 64];
            o1[0] = make_ulonglong2(acc1[0], acc1[1]);
            o1[1] = make_ulonglong2(acc1[2], acc1[3]);
            o1[2] = make_ulonglong2(acc1[4], acc1[5]);
            o1[3] = make_ulonglong2(acc1[6], acc1[7]);
        }
    }
}

// ---------------- conv 64->64, HxH SAME ----------------
// grid (tiles, 800), 128 threads. Tile 8x8 px x 64 cout; per thread 4px x 4 cout-pairs.
__global__ void __launch_bounds__(128)
k_conv64(const float* __restrict__ in, float* __restrict__ out,
         const float* __restrict__ w, const float* __restrict__ bias,
         int H, int tilesX) {
    __shared__ float s_in[10 * 10 * 16];
    __shared__ float s_w[9 * 16 * 64];
    const int tid = threadIdx.x;
    const int im = blockIdx.y;
    const int tile = blockIdx.x;
    const int tx0 = (tile % tilesX) * 8, ty0 = (tile / tilesX) * 8;
    const int HW = H * H;
    const int tp = tid & 15, tc = tid >> 4;
    const int prow = tp >> 1, col0 = (tp & 1) * 4;
    const float* imbase = in + (size_t)im * HW * 64;

    u64 acc2[4][4];   // [pixel][cout-pair]
#pragma unroll
    for (int jp = 0; jp < 4; ++jp) {
        u64 bb = pack2(bias[tc * 8 + 2 * jp], bias[tc * 8 + 2 * jp + 1]);
#pragma unroll
        for (int i = 0; i < 4; ++i) acc2[i][jp] = bb;
    }

    for (int cc = 0; cc < 4; ++cc) {
        __syncthreads();
        for (int i = tid; i < 1600; i += 128) {
            int ci = i & 15, c = (i >> 4) % 10, r = i / 160;
            int gy = ty0 + r - 1, gx = tx0 + c - 1;
            float v = 0.f;
            if (gy >= 0 && gy < H && gx >= 0 && gx < H)
                v = imbase[(size_t)(gy * H + gx) * 64 + cc * 16 + ci];
            s_in[i] = v;
        }
        for (int i4 = tid; i4 < 2304; i4 += 128) {
            int co4 = i4 & 15, ci = (i4 >> 4) & 15, k9 = i4 >> 8;
            *(float4*)&s_w[i4 * 4] =
                *(const float4*)&w[((size_t)(k9 * 64 + cc * 16 + ci)) * 64 + co4 * 4];
        }
        __syncthreads();

#pragma unroll 1
        for (int k9 = 0; k9 < 9; ++k9) {
            int ky = k9 / 3, kx = k9 - ky * 3;
            const float* sr = &s_in[((prow + ky) * 10 + col0 + kx) * 16];
            const float* wr = &s_w[k9 * 1024 + tc * 8];
#pragma unroll
            for (int c4 = 0; c4 < 4; ++c4) {
                float as[4][4];
#pragma unroll
                for (int i = 0; i < 4; ++i) {
                    float4 t = *(const float4*)(sr + i * 16 + c4 * 4);
                    as[i][0] = t.x; as[i][1] = t.y; as[i][2] = t.z; as[i][3] = t.w;
                }
#pragma unroll
                for (int cj = 0; cj < 4; ++cj) {
                    const ulonglong2* wp2 = (const ulonglong2*)(wr + (c4 * 4 + cj) * 64);
                    ulonglong2 wA = wp2[0], wB = wp2[1];   // cout pairs 01,23,45,67
#pragma unroll
                    for (int i = 0; i < 4; ++i) {
                        u64 a2 = pack_dup(as[i][cj]);
                        fma2(acc2[i][0], a2, wA.x);
                        fma2(acc2[i][1], a2, wA.y);
                        fma2(acc2[i][2], a2, wB.x);
                        fma2(acc2[i][3], a2, wB.y);
                    }
                }
            }
        }
    }

    int oy = ty0 + prow;
    if (oy < H) {
#pragma unroll
        for (int i = 0; i < 4; ++i) {
            int ox = tx0 + col0 + i;
            if (ox < H) {
                float* o = &out[((size_t)im * HW + (size_t)oy * H + ox) * 64 + tc * 8];
                *(ulonglong2*)o       = make_ulonglong2(acc2[i][0], acc2[i][1]);
                *(ulonglong2*)(o + 4) = make_ulonglong2(acc2[i][2], acc2[i][3]);
            }
        }
    }
}

// stats pass 1: per-block partials. grid (64, 25 groups), 256 threads.
__global__ void k_stats(const float* __restrict__ conv, int HW) {
    __shared__ float ss[256], sq[256];
    int g = blockIdx.y, blk = blockIdx.x, tid = threadIdx.x;
    int c = tid & 63, l = tid >> 6;
    int P = 32 * HW;
    float s = 0.f, q = 0.f;
    for (int p = blk * 4 + l; p < P; p += 64 * 4) {
        float v = conv[((size_t)g * P + p) * 64 + c];
        s += v; q += v * v;
    }
    ss[tid] = s; sq[tid] = q;
    __syncthreads();
    if (tid < 64) {
        s = ss[tid] + ss[tid + 64] + ss[tid + 128] + ss[tid + 192];
        q = sq[tid] + sq[tid + 64] + sq[tid + 128] + sq[tid + 192];
        g_spart[((size_t)blk * 25 + g) * 128 + tid * 2]     = s;
        g_spart[((size_t)blk * 25 + g) * 128 + tid * 2 + 1] = q;
    }
}

// stats pass 2: fixed-order reduction of 64 partials. 1600 (g,c) pairs.
__global__ void k_sreduce() {
    int i = blockIdx.x * 256 + threadIdx.x;   // i = g*64+c
    if (i >= 1600) return;
    int g = i >> 6, c = i & 63;
    float s = 0.f, q = 0.f;
#pragma unroll 4
    for (int blk = 0; blk < 64; ++blk) {
        s += g_spart[((size_t)blk * 25 + g) * 128 + c * 2];
        q += g_spart[((size_t)blk * 25 + g) * 128 + c * 2 + 1];
    }
    g_stats[i * 2] = s;
    g_stats[i * 2 + 1] = q;
}

// BN + relu + 2x2/2 maxpool. total = 800*Hout*Hout*64
__global__ void k_bnpool(const float* __restrict__ conv, float* __restrict__ out,
                         const float* __restrict__ gam, const float* __restrict__ bet,
                         int Hin, int Hout, float invcnt, int total) {
    int i = blockIdx.x * 256 + threadIdx.x;
    if (i >= total) return;
    int c = i & 63;
    int t = i >> 6;
    int xo = t % Hout; t /= Hout;
    int yo = t % Hout;
    int im = t / Hout;
    int g = im >> 5;
    float s = g_stats[(g * 64 + c) * 2];
    float qq = g_stats[(g * 64 + c) * 2 + 1];
    float mean = s * invcnt;
    float var = qq * invcnt - mean * mean;
    float scale = gam[c] * rsqrtf(var + 1e-3f);
    float shift = bet[c] - mean * scale;
    size_t base = (((size_t)im * Hin + 2 * yo) * Hin + 2 * xo) * 64 + c;
    float v00 = fmaxf(conv[base] * scale + shift, 0.f);
    float v01 = fmaxf(conv[base + 64] * scale + shift, 0.f);
    float v10 = fmaxf(conv[base + (size_t)Hin * 64] * scale + shift, 0.f);
    float v11 = fmaxf(conv[base + (size_t)Hin * 64 + 64] * scale + shift, 0.f);
    out[i] = fmaxf(fmaxf(v00, v01), fmaxf(v10, v11));
}

// x @ Wx + b, both directions. grid (200, 2), 128 threads, 4 images/block.
__global__ void k_xw(const float* __restrict__ fk, const float* __restrict__ fb,
                     const float* __restrict__ bk, const float* __restrict__ bb) {
    __shared__ float es[4 * 1600];
    int tid = threadIdx.x, dir = blockIdx.y, im0 = blockIdx.x * 4;
    const float* W = dir ? bk : fk;
    const float* B = dir ? bb : fb;
    for (int i = tid; i < 6400; i += 128) es[i] = g_emb[(size_t)im0 * 1600 + i];
    __syncthreads();
    float a0 = 0.f, a1 = 0.f, a2 = 0.f, a3 = 0.f;
#pragma unroll 4
    for (int k = 0; k < 1600; ++k) {
        float wv = W[(size_t)k * 128 + tid];
        a0 += es[k] * wv;
        a1 += es[1600 + k] * wv;
        a2 += es[3200 + k] * wv;
        a3 += es[4800 + k] * wv;
    }
    float bv = B[tid];
    g_xw[((size_t)dir * 800 + im0 + 0) * 128 + tid] = a0 + bv;
    g_xw[((size_t)dir * 800 + im0 + 1) * 128 + tid] = a1 + bv;
    g_xw[((size_t)dir * 800 + im0 + 2) * 128 + tid] = a2 + bv;
    g_xw[((size_t)dir * 800 + im0 + 3) * 128 + tid] = a3 + bv;
}

// BiLSTM over the 32-step episode axis. grid (5 queries, 2 dirs), 128 threads.
__global__ void k_lstm(const float* __restrict__ fr, const float* __restrict__ br) {
    __shared__ float wh[32 * 128];
    __shared__ float hs[672], cs[672], zs[21 * 128];
    int q = blockIdx.x, dir = blockIdx.y, tid = threadIdx.x;
    const float* R = dir ? br : fr;
    for (int i = tid; i < 4096; i += 128) wh[i] = R[i];
    for (int i = tid; i < 672; i += 128) { hs[i] = 0.f; cs[i] = 0.f; }
    __syncthreads();

    for (int t = 0; t < 32; ++t) {
        int e = dir ? 31 - t : t;
#pragma unroll 3
        for (int j = 0; j < 21; ++j) {
            int gj = (j < 20) ? j : 20 + q;
            float z = g_xw[((size_t)dir * 800 + gj * 32 + e) * 128 + tid];
            float z1 = 0.f;
#pragma unroll
            for (int k = 0; k < 32; k += 2) {
                z  += hs[j * 32 + k]     * wh[k * 128 + tid];
                z1 += hs[j * 32 + k + 1] * wh[(k + 1) * 128 + tid];
            }
            zs[j * 128 + tid] = z + z1;
        }
        __syncthreads();
        for (int idx = tid; idx < 672; idx += 128) {
            int j = idx >> 5, u = idx & 31;
            float zi = zs[j * 128 + u];
            float zf = zs[j * 128 + 32 + u];
            float zg = zs[j * 128 + 64 + u];
            float zo = zs[j * 128 + 96 + u];
            float c = sigf(zf) * cs[idx] + sigf(zi) * tanhf(zg);
            float h = sigf(zo) * tanhf(c);
            cs[idx] = c; hs[idx] = h;
            g_outs[(((size_t)q * 21 + j) * 32 + e) * 64 + dir * 32 + u] = h;
        }
        __syncthreads();
    }
}

// Epilogue: cosine-attention, softmax, preds, CE, acc. Single block, deterministic.
__global__ void k_final(const int* __restrict__ ys, const int* __restrict__ yq,
                        float* __restrict__ out) {
    __shared__ float s_ce[160];
    __shared__ float s_eq[160];
    int t = threadIdx.x;
    if (t < 160) {
        int q = t / 32, b = t % 32;
        const float* qp = &g_outs[(((size_t)q * 21 + 20) * 32 + b) * 64];
        float val[20];
        for (int s = 0; s < 20; ++s) {
            const float* sp = &g_outs[(((size_t)q * 21 + s) * 32 + b) * 64];
            float dot = 0.f, ssq = 0.f;
            for (int d = 0; d < 64; ++d) {
                float sv = sp[d];
                dot += qp[d] * sv;
                ssq += sv * sv;
            }
            val[s] = dot * rsqrtf(fmaxf(ssq, 1e-10f));
        }
        float m = -1e30f;
        for (int s = 0; s < 20; ++s) m = fmaxf(m, val[s]);
        float sum = 0.f;
        for (int s = 0; s < 20; ++s) { val[s] = expf(val[s] - m); sum += val[s]; }
        float inv = 1.f / sum;

        float preds[20];
        for (int w = 0; w < 20; ++w) preds[w] = 0.f;
        for (int s = 0; s < 20; ++s) preds[ys[b * 20 + s]] += val[s] * inv;

        int lbl = yq[b * 5 + q];
        float p = fminf(fmaxf(preds[lbl], 1e-7f), 1.f - 1e-7f);
        s_ce[t] = -logf(p);

        int am = 0; float bv = preds[0];
        for (int w = 1; w < 20; ++w) if (preds[w] > bv) { bv = preds[w]; am = w; }
        s_eq[t] = (am == lbl) ? 1.f : 0.f;
    }
    __syncthreads();
    if (t < 32) {
        float ce = 0.f;
        for (int q = 0; q < 5; ++q) ce += s_ce[q * 32 + t];
        out[t] = ce * 0.2f;
    }
    if (t == 32) {
        float a = 0.f;
        for (int i = 0; i < 160; ++i) a += s_eq[i];
        out[32] = a * (1.f / 160.f);
    }
}

extern "C" void kernel_launch(void* const* d_in, const int* in_sizes, int n_in,
                              void* d_out, int out_size) {
    const float* xs  = (const float*)d_in[0];
    const int*   ysup= (const int*)  d_in[1];
    const float* xq  = (const float*)d_in[2];
    const int*   yqry= (const int*)  d_in[3];
    const float* k1 = (const float*)d_in[4];
    const float* b1 = (const float*)d_in[5];
    const float* g1 = (const float*)d_in[6];
    const float* be1= (const float*)d_in[7];
    const float* k2 = (const float*)d_in[8];
    const float* b2 = (const float*)d_in[9];
    const float* g2 = (const float*)d_in[10];
    const float* be2= (const float*)d_in[11];
    const float* k3 = (const float*)d_in[12];
    const float* b3 = (const float*)d_in[13];
    const float* g3 = (const float*)d_in[14];
    const float* be3= (const float*)d_in[15];
    const float* k4 = (const float*)d_in[16];
    const float* b4 = (const float*)d_in[17];
    const float* g4 = (const float*)d_in[18];
    const float* be4= (const float*)d_in[19];
    const float* fk = (const float*)d_in[20];
    const float* fr = (const float*)d_in[21];
    const float* fb = (const float*)d_in[22];
    const float* bk = (const float*)d_in[23];
    const float* br = (const float*)d_in[24];
    const float* bb = (const float*)d_in[25];
    float* out = (float*)d_out;

    float* cv; cudaGetSymbolAddress((void**)&cv, g_conv);
    float* p1; cudaGetSymbolAddress((void**)&p1, g_p1);
    float* p2; cudaGetSymbolAddress((void**)&p2, g_p2);
    float* p3; cudaGetSymbolAddress((void**)&p3, g_p3);
    float* em; cudaGetSymbolAddress((void**)&em, g_emb);

    // ---- layer 1: 84x84, 3->64 ----
    k_conv1<<<dim3(21, 800), 256>>>(xs, xq, k1, b1);
    k_stats<<<dim3(64, 25), 256>>>(cv, 84 * 84);
    k_sreduce<<<7, 256>>>();
    k_bnpool<<<(800*42*42*64 + 255) / 256, 256>>>(cv, p1, g1, be1, 84, 42,
                                                  1.f / (32.f * 7056.f), 800*42*42*64);
    // ---- layer 2: 42x42 ----
    k_conv64<<<dim3(36, 800), 128>>>(p1, cv, k2, b2, 42, 6);
    k_stats<<<dim3(64, 25), 256>>>(cv, 42 * 42);
    k_sreduce<<<7, 256>>>();
    k_bnpool<<<(800*21*21*64 + 255) / 256, 256>>>(cv, p2, g2, be2, 42, 21,
                                                  1.f / (32.f * 1764.f), 800*21*21*64);
    // ---- layer 3: 21x21 ----
    k_conv64<<<dim3(9, 800), 128>>>(p2, cv, k3, b3, 21, 3);
    k_stats<<<dim3(64, 25), 256>>>(cv, 21 * 21);
    k_sreduce<<<7, 256>>>();
    k_bnpool<<<(800*10*10*64 + 255) / 256, 256>>>(cv, p3, g3, be3, 21, 10,
                                                  1.f / (32.f * 441.f), 800*10*10*64);
    // ---- layer 4: 10x10 ----
    k_conv64<<<dim3(4, 800), 128>>>(p3, cv, k4, b4, 10, 2);
    k_stats<<<dim3(64, 25), 256>>>(cv, 10 * 10);
    k_sreduce<<<7, 256>>>();
    k_bnpool<<<(800*5*5*64 + 255) / 256, 256>>>(cv, em, g4, be4, 10, 5,
                                                1.f / (32.f * 100.f), 800*5*5*64);
    // ---- LSTM input GEMM, BiLSTM, epilogue ----
    k_xw<<<dim3(200, 2), 128>>>(fk, fb, bk, bb);
    k_lstm<<<dim3(5, 2), 128>>>(fr, br);
    k_final<<<1, 192>>>(ysup, yqry, out);
}

// round 14
// speedup vs baseline: 1.8920x; 1.8920x over previous
#include <cuda_runtime.h>
#include <math.h>

// ---------------- static scratch (no allocations allowed) ----------------
__device__ float g_conv[(size_t)800 * 84 * 84 * 64];
__device__ float g_p1[(size_t)800 * 42 * 42 * 64];
__device__ float g_p2[(size_t)800 * 21 * 21 * 64];
__device__ float g_p3[(size_t)800 * 10 * 10 * 64];
__device__ float g_emb[(size_t)800 * 1600];
__device__ float g_xw[(size_t)2 * 800 * 128];
__device__ float g_spart[64 * 25 * 64 * 2];
__device__ float g_stats[25 * 64 * 2];
__device__ float g_outs[(size_t)5 * 21 * 32 * 64];

__device__ __forceinline__ float sigf(float x) { return 1.f / (1.f + expf(-x)); }

typedef unsigned long long u64;
__device__ __forceinline__ u64 pack_dup(float x) {
    u64 r; asm("mov.b64 %0, {%1, %1};" : "=l"(r) : "f"(x)); return r;
}
__device__ __forceinline__ u64 pack2(float lo, float hi) {
    u64 r; asm("mov.b64 %0, {%1, %2};" : "=l"(r) : "f"(lo), "f"(hi)); return r;
}
__device__ __forceinline__ void fma2(u64& d, u64 a, u64 b) {
    asm("fma.rn.f32x2 %0, %1, %2, %0;" : "+l"(d) : "l"(a), "l"(b));
}

// tf32 helpers
__device__ __forceinline__ unsigned f2tf(float x) {
    unsigned r; asm("cvt.rna.tf32.f32 %0, %1;" : "=r"(r) : "f"(x)); return r;
}
__device__ __forceinline__ void tf32_split(float x, float& hi, float& lo) {
    unsigned h = f2tf(x);
    float hf = __uint_as_float(h);
    unsigned l = f2tf(x - hf);
    hi = hf; lo = __uint_as_float(l);
}
__device__ __forceinline__ void mma_tf32(float c[4], const unsigned a[4], unsigned b0, unsigned b1) {
    asm("mma.sync.aligned.m16n8k8.row.col.f32.tf32.tf32.f32 "
        "{%0,%1,%2,%3},{%4,%5,%6,%7},{%8,%9},{%0,%1,%2,%3};"
        : "+f"(c[0]), "+f"(c[1]), "+f"(c[2]), "+f"(c[3])
        : "r"(a[0]), "r"(a[1]), "r"(a[2]), "r"(a[3]), "r"(b0), "r"(b1));
}

// ---------------- conv1: 3->64, 84x84 SAME (fp32, unchanged) ----------------
__global__ void __launch_bounds__(256, 4)
k_conv1(const float* __restrict__ xs, const float* __restrict__ xq,
        const float* __restrict__ w, const float* __restrict__ bias) {
    __shared__ float s_in[6 * 86 * 3];
    __shared__ float s_w[27 * 64];
    const int tid = threadIdx.x;
    const int im = blockIdx.y;
    const int strip = blockIdx.x;
    const int g = im >> 5, n = im & 31;
    const float* src = (g < 20) ? xs + (size_t)(n * 20 + g) * (84 * 84 * 3)
                                : xq + (size_t)(n * 5 + (g - 20)) * (84 * 84 * 3);

    for (int i = tid; i < 27 * 64; i += 256) s_w[i] = w[i];
    for (int i = tid; i < 6 * 86 * 3; i += 256) {
        int ci = i % 3; int c = (i / 3) % 86; int r = i / (3 * 86);
        int gy = strip * 4 - 1 + r, gx = c - 1;
        float v = 0.f;
        if (gy >= 0 && gy < 84 && gx >= 0 && gx < 84) v = src[(gy * 84 + gx) * 3 + ci];
        s_in[i] = v;
    }
    __syncthreads();

    const int cg = tid & 3;
    const int ppb = tid >> 2;
    u64 b2[8];
#pragma unroll
    for (int jp = 0; jp < 8; ++jp)
        b2[jp] = pack2(bias[cg * 16 + 2 * jp], bias[cg * 16 + 2 * jp + 1]);

    for (int it = 0; it < 3; ++it) {
        int pp = ppb + it * 64;
        if (pp < 168) {
            int prow = pp / 42;
            int col0 = (pp % 42) * 2;
            u64 acc0[8], acc1[8];
#pragma unroll
            for (int jp = 0; jp < 8; ++jp) { acc0[jp] = b2[jp]; acc1[jp] = b2[jp]; }
#pragma unroll
            for (int k = 0; k < 27; ++k) {
                int ky = k / 9, kx = (k % 9) / 3, ci = k % 3;
                u64 a0 = pack_dup(s_in[((prow + ky) * 86 + (col0 + kx)) * 3 + ci]);
                u64 a1 = pack_dup(s_in[((prow + ky) * 86 + (col0 + 1 + kx)) * 3 + ci]);
                const ulonglong2* wp = (const ulonglong2*)&s_w[k * 64 + cg * 16];
                ulonglong2 wA = wp[0], wB = wp[1], wC = wp[2], wD = wp[3];
                fma2(acc0[0], a0, wA.x); fma2(acc1[0], a1, wA.x);
                fma2(acc0[1], a0, wA.y); fma2(acc1[1], a1, wA.y);
                fma2(acc0[2], a0, wB.x); fma2(acc1[2], a1, wB.x);
                fma2(acc0[3], a0, wB.y); fma2(acc1[3], a1, wB.y);
                fma2(acc0[4], a0, wC.x); fma2(acc1[4], a1, wC.x);
                fma2(acc0[5], a0, wC.y); fma2(acc1[5], a1, wC.y);
                fma2(acc0[6], a0, wD.x); fma2(acc1[6], a1, wD.x);
                fma2(acc0[7], a0, wD.y); fma2(acc1[7], a1, wD.y);
            }
            int oy = strip * 4 + prow;
            size_t base = ((size_t)im * 7056 + (size_t)oy * 84 + col0) * 64 + cg * 16;
            ulonglong2* o0 = (ulonglong2*)&g_conv[base];
            o0[0] = make_ulonglong2(acc0[0], acc0[1]);
            o0[1] = make_ulonglong2(acc0[2], acc0[3]);
            o0[2] = make_ulonglong2(acc0[4], acc0[5]);
            o0[3] = make_ulonglong2(acc0[6], acc0[7]);
            ulonglong2* o1 = (ulonglong2*)&g_conv[base + 64];
            o1[0] = make_ulonglong2(acc1[0], acc1[1]);
            o1[1] = make_ulonglong2(acc1[2], acc1[3]);
            o1[2] = make_ulonglong2(acc1[4], acc1[5]);
            o1[3] = make_ulonglong2(acc1[6], acc1[7]);
        }
    }
}

// ---------------- conv 64->64 via 3xTF32 mma.sync ----------------
// grid (tiles, 800), 128 threads = 4 warps. Tile 8x8 px x 64 cout.
#define BSTR 70   // s_b row stride (floats) — 2-way LDS conflict max, fits 48KB
__global__ void __launch_bounds__(128)
k_conv64_mma(const float* __restrict__ in, float* __restrict__ out,
             const float* __restrict__ w, const float* __restrict__ bias,
             int H, int tilesX) {
    __shared__ float s_a[2][100 * 9];        // [hi/lo][(py*10+px)*9 + cin]  7.2KB
    __shared__ float s_b[2][72 * BSTR];      // [hi/lo][(k9*8+cin)*BSTR + cout] 40.3KB
    const int tid = threadIdx.x;
    const int im = blockIdx.y;
    const int tile = blockIdx.x;
    const int tx0 = (tile % tilesX) * 8, ty0 = (tile / tilesX) * 8;
    const int HW = H * H;
    const int warp = tid >> 5, lane = tid & 31;
    const int g = lane >> 2, t = lane & 3;
    const float* imbase = in + (size_t)im * HW * 64;

    // C fragments: 8 n-tiles x 4 regs. cols: c0/c2 -> nt*8+2t, c1/c3 -> +1
    float c[8][4];
#pragma unroll
    for (int nt = 0; nt < 8; ++nt) {
        float bv0 = bias[nt * 8 + 2 * t];
        float bv1 = bias[nt * 8 + 2 * t + 1];
        c[nt][0] = bv0; c[nt][1] = bv1; c[nt][2] = bv0; c[nt][3] = bv1;
    }

    const int py1 = 2 * warp;          // A row m=g -> tile row 2w, col g
    const int px1 = g;

    for (int cc = 0; cc < 8; ++cc) {
        __syncthreads();
        // stage activations (10x10 halo, 8 cin) with hi/lo split
        for (int i = tid; i < 800; i += 128) {
            int ci = i & 7, pxlin = i >> 3;
            int r = pxlin / 10, col = pxlin % 10;
            int gy = ty0 + r - 1, gx = tx0 + col - 1;
            float v = 0.f;
            if (gy >= 0 && gy < H && gx >= 0 && gx < H)
                v = imbase[(size_t)(gy * H + gx) * 64 + cc * 8 + ci];
            float hi, lo; tf32_split(v, hi, lo);
            s_a[0][pxlin * 9 + ci] = hi;
            s_a[1][pxlin * 9 + ci] = lo;
        }
        // stage weights (9 taps x 8 cin x 64 cout) with hi/lo split
        for (int i = tid; i < 4608; i += 128) {
            int co = i & 63, row = i >> 6;          // row = k9*8 + cin
            int k9 = row >> 3, ci = row & 7;
            float v = w[((size_t)(k9 * 64 + cc * 8 + ci)) * 64 + co];
            float hi, lo; tf32_split(v, hi, lo);
            s_b[0][row * BSTR + co] = hi;
            s_b[1][row * BSTR + co] = lo;
        }
        __syncthreads();

#pragma unroll 1
        for (int k9 = 0; k9 < 9; ++k9) {
            int ky = k9 / 3, kx = k9 - 3 * ky;
            int ra = ((py1 + ky) * 10 + px1 + kx) * 9;          // A rows m=g
            int rb = ((py1 + 1 + ky) * 10 + px1 + kx) * 9;      // A rows m=g+8
            unsigned a_hi[4], a_lo[4];
            a_hi[0] = __float_as_uint(s_a[0][ra + t]);
            a_hi[1] = __float_as_uint(s_a[0][rb + t]);
            a_hi[2] = __float_as_uint(s_a[0][ra + t + 4]);
            a_hi[3] = __float_as_uint(s_a[0][rb + t + 4]);
            a_lo[0] = __float_as_uint(s_a[1][ra + t]);
            a_lo[1] = __float_as_uint(s_a[1][rb + t]);
            a_lo[2] = __float_as_uint(s_a[1][ra + t + 4]);
            a_lo[3] = __float_as_uint(s_a[1][rb + t + 4]);
            int wr0 = (k9 * 8 + t) * BSTR;
            int wr1 = (k9 * 8 + t + 4) * BSTR;
#pragma unroll
            for (int nt = 0; nt < 8; ++nt) {
                int nb = nt * 8 + g;
                unsigned bh0 = __float_as_uint(s_b[0][wr0 + nb]);
                unsigned bh1 = __float_as_uint(s_b[0][wr1 + nb]);
                unsigned bl0 = __float_as_uint(s_b[1][wr0 + nb]);
                unsigned bl1 = __float_as_uint(s_b[1][wr1 + nb]);
                mma_tf32(c[nt], a_hi, bh0, bh1);   // hi*hi
                mma_tf32(c[nt], a_lo, bh0, bh1);   // lo*hi
                mma_tf32(c[nt], a_hi, bl0, bl1);   // hi*lo
            }
        }
    }

    // epilogue: write 16px x 64cout per warp
    int ox = tx0 + px1;
    int oy1 = ty0 + py1;
    int oy2 = oy1 + 1;
    if (ox < H) {
        if (oy1 < H) {
            float* o = &out[((size_t)im * HW + (size_t)oy1 * H + ox) * 64];
#pragma unroll
            for (int nt = 0; nt < 8; ++nt)
                *(float2*)&o[nt * 8 + 2 * t] = make_float2(c[nt][0], c[nt][1]);
        }
        if (oy2 < H) {
            float* o = &out[((size_t)im * HW + (size_t)oy2 * H + ox) * 64];
#pragma unroll
            for (int nt = 0; nt < 8; ++nt)
                *(float2*)&o[nt * 8 + 2 * t] = make_float2(c[nt][2], c[nt][3]);
        }
    }
}

// stats pass 1: per-block partials. grid (64, 25 groups), 256 threads.
__global__ void k_stats(const float* __restrict__ conv, int HW) {
    __shared__ float ss[256], sq[256];
    int g = blockIdx.y, blk = blockIdx.x, tid = threadIdx.x;
    int c = tid & 63, l = tid >> 6;
    int P = 32 * HW;
    float s = 0.f, q = 0.f;
    for (int p = blk * 4 + l; p < P; p += 64 * 4) {
        float v = conv[((size_t)g * P + p) * 64 + c];
        s += v; q += v * v;
    }
    ss[tid] = s; sq[tid] = q;
    __syncthreads();
    if (tid < 64) {
        s = ss[tid] + ss[tid + 64] + ss[tid + 128] + ss[tid + 192];
        q = sq[tid] + sq[tid + 64] + sq[tid + 128] + sq[tid + 192];
        g_spart[((size_t)blk * 25 + g) * 128 + tid * 2]     = s;
        g_spart[((size_t)blk * 25 + g) * 128 + tid * 2 + 1] = q;
    }
}

__global__ void k_sreduce() {
    int i = blockIdx.x * 256 + threadIdx.x;
    if (i >= 1600) return;
    int g = i >> 6, c = i & 63;
    float s = 0.f, q = 0.f;
#pragma unroll 4
    for (int blk = 0; blk < 64; ++blk) {
        s += g_spart[((size_t)blk * 25 + g) * 128 + c * 2];
        q += g_spart[((size_t)blk * 25 + g) * 128 + c * 2 + 1];
    }
    g_stats[i * 2] = s;
    g_stats[i * 2 + 1] = q;
}

__global__ void k_bnpool(const float* __restrict__ conv, float* __restrict__ out,
                         const float* __restrict__ gam, const float* __restrict__ bet,
                         int Hin, int Hout, float invcnt, int total) {
    int i = blockIdx.x * 256 + threadIdx.x;
    if (i >= total) return;
    int c = i & 63;
    int t = i >> 6;
    int xo = t % Hout; t /= Hout;
    int yo = t % Hout;
    int im = t / Hout;
    int g = im >> 5;
    float s = g_stats[(g * 64 + c) * 2];
    float qq = g_stats[(g * 64 + c) * 2 + 1];
    float mean = s * invcnt;
    float var = qq * invcnt - mean * mean;
    float scale = gam[c] * rsqrtf(var + 1e-3f);
    float shift = bet[c] - mean * scale;
    size_t base = (((size_t)im * Hin + 2 * yo) * Hin + 2 * xo) * 64 + c;
    float v00 = fmaxf(conv[base] * scale + shift, 0.f);
    float v01 = fmaxf(conv[base + 64] * scale + shift, 0.f);
    float v10 = fmaxf(conv[base + (size_t)Hin * 64] * scale + shift, 0.f);
    float v11 = fmaxf(conv[base + (size_t)Hin * 64 + 64] * scale + shift, 0.f);
    out[i] = fmaxf(fmaxf(v00, v01), fmaxf(v10, v11));
}

__global__ void k_xw(const float* __restrict__ fk, const float* __restrict__ fb,
                     const float* __restrict__ bk, const float* __restrict__ bb) {
    __shared__ float es[4 * 1600];
    int tid = threadIdx.x, dir = blockIdx.y, im0 = blockIdx.x * 4;
    const float* W = dir ? bk : fk;
    const float* B = dir ? bb : fb;
    for (int i = tid; i < 6400; i += 128) es[i] = g_emb[(size_t)im0 * 1600 + i];
    __syncthreads();
    float a0 = 0.f, a1 = 0.f, a2 = 0.f, a3 = 0.f;
#pragma unroll 4
    for (int k = 0; k < 1600; ++k) {
        float wv = W[(size_t)k * 128 + tid];
        a0 += es[k] * wv;
        a1 += es[1600 + k] * wv;
        a2 += es[3200 + k] * wv;
        a3 += es[4800 + k] * wv;
    }
    float bv = B[tid];
    g_xw[((size_t)dir * 800 + im0 + 0) * 128 + tid] = a0 + bv;
    g_xw[((size_t)dir * 800 + im0 + 1) * 128 + tid] = a1 + bv;
    g_xw[((size_t)dir * 800 + im0 + 2) * 128 + tid] = a2 + bv;
    g_xw[((size_t)dir * 800 + im0 + 3) * 128 + tid] = a3 + bv;
}

__global__ void k_lstm(const float* __restrict__ fr, const float* __restrict__ br) {
    __shared__ float wh[32 * 128];
    __shared__ float hs[672], cs[672], zs[21 * 128];
    int q = blockIdx.x, dir = blockIdx.y, tid = threadIdx.x;
    const float* R = dir ? br : fr;
    for (int i = tid; i < 4096; i += 128) wh[i] = R[i];
    for (int i = tid; i < 672; i += 128) { hs[i] = 0.f; cs[i] = 0.f; }
    __syncthreads();

    for (int t = 0; t < 32; ++t) {
        int e = dir ? 31 - t : t;
#pragma unroll 3
        for (int j = 0; j < 21; ++j) {
            int gj = (j < 20) ? j : 20 + q;
            float z = g_xw[((size_t)dir * 800 + gj * 32 + e) * 128 + tid];
            float z1 = 0.f;
#pragma unroll
            for (int k = 0; k < 32; k += 2) {
                z  += hs[j * 32 + k]     * wh[k * 128 + tid];
                z1 += hs[j * 32 + k + 1] * wh[(k + 1) * 128 + tid];
            }
            zs[j * 128 + tid] = z + z1;
        }
        __syncthreads();
        for (int idx = tid; idx < 672; idx += 128) {
            int j = idx >> 5, u = idx & 31;
            float zi = zs[j * 128 + u];
            float zf = zs[j * 128 + 32 + u];
            float zg = zs[j * 128 + 64 + u];
            float zo = zs[j * 128 + 96 + u];
            float c = sigf(zf) * cs[idx] + sigf(zi) * tanhf(zg);
            float h = sigf(zo) * tanhf(c);
            cs[idx] = c; hs[idx] = h;
            g_outs[(((size_t)q * 21 + j) * 32 + e) * 64 + dir * 32 + u] = h;
        }
        __syncthreads();
    }
}

__global__ void k_final(const int* __restrict__ ys, const int* __restrict__ yq,
                        float* __restrict__ out) {
    __shared__ float s_ce[160];
    __shared__ float s_eq[160];
    int t = threadIdx.x;
    if (t < 160) {
        int q = t / 32, b = t % 32;
        const float* qp = &g_outs[(((size_t)q * 21 + 20) * 32 + b) * 64];
        float val[20];
        for (int s = 0; s < 20; ++s) {
            const float* sp = &g_outs[(((size_t)q * 21 + s) * 32 + b) * 64];
            float dot = 0.f, ssq = 0.f;
            for (int d = 0; d < 64; ++d) {
                float sv = sp[d];
                dot += qp[d] * sv;
                ssq += sv * sv;
            }
            val[s] = dot * rsqrtf(fmaxf(ssq, 1e-10f));
        }
        float m = -1e30f;
        for (int s = 0; s < 20; ++s) m = fmaxf(m, val[s]);
        float sum = 0.f;
        for (int s = 0; s < 20; ++s) { val[s] = expf(val[s] - m); sum += val[s]; }
        float inv = 1.f / sum;

        float preds[20];
        for (int w = 0; w < 20; ++w) preds[w] = 0.f;
        for (int s = 0; s < 20; ++s) preds[ys[b * 20 + s]] += val[s] * inv;

        int lbl = yq[b * 5 + q];
        float p = fminf(fmaxf(preds[lbl], 1e-7f), 1.f - 1e-7f);
        s_ce[t] = -logf(p);

        int am = 0; float bv = preds[0];
        for (int w = 1; w < 20; ++w) if (preds[w] > bv) { bv = preds[w]; am = w; }
        s_eq[t] = (am == lbl) ? 1.f : 0.f;
    }
    __syncthreads();
    if (t < 32) {
        float ce = 0.f;
        for (int q = 0; q < 5; ++q) ce += s_ce[q * 32 + t];
        out[t] = ce * 0.2f;
    }
    if (t == 32) {
        float a = 0.f;
        for (int i = 0; i < 160; ++i) a += s_eq[i];
        out[32] = a * (1.f / 160.f);
    }
}

extern "C" void kernel_launch(void* const* d_in, const int* in_sizes, int n_in,
                              void* d_out, int out_size) {
    const float* xs  = (const float*)d_in[0];
    const int*   ysup= (const int*)  d_in[1];
    const float* xq  = (const float*)d_in[2];
    const int*   yqry= (const int*)  d_in[3];
    const float* k1 = (const float*)d_in[4];
    const float* b1 = (const float*)d_in[5];
    const float* g1 = (const float*)d_in[6];
    const float* be1= (const float*)d_in[7];
    const float* k2 = (const float*)d_in[8];
    const float* b2 = (const float*)d_in[9];
    const float* g2 = (const float*)d_in[10];
    const float* be2= (const float*)d_in[11];
    const float* k3 = (const float*)d_in[12];
    const float* b3 = (const float*)d_in[13];
    const float* g3 = (const float*)d_in[14];
    const float* be3= (const float*)d_in[15];
    const float* k4 = (const float*)d_in[16];
    const float* b4 = (const float*)d_in[17];
    const float* g4 = (const float*)d_in[18];
    const float* be4= (const float*)d_in[19];
    const float* fk = (const float*)d_in[20];
    const float* fr = (const float*)d_in[21];
    const float* fb = (const float*)d_in[22];
    const float* bk = (const float*)d_in[23];
    const float* br = (const float*)d_in[24];
    const float* bb = (const float*)d_in[25];
    float* out = (float*)d_out;

    float* cv; cudaGetSymbolAddress((void**)&cv, g_conv);
    float* p1; cudaGetSymbolAddress((void**)&p1, g_p1);
    float* p2; cudaGetSymbolAddress((void**)&p2, g_p2);
    float* p3; cudaGetSymbolAddress((void**)&p3, g_p3);
    float* em; cudaGetSymbolAddress((void**)&em, g_emb);

    // ---- layer 1: 84x84, 3->64 ----
    k_conv1<<<dim3(21, 800), 256>>>(xs, xq, k1, b1);
    k_stats<<<dim3(64, 25), 256>>>(cv, 84 * 84);
    k_sreduce<<<7, 256>>>();
    k_bnpool<<<(800*42*42*64 + 255) / 256, 256>>>(cv, p1, g1, be1, 84, 42,
                                                  1.f / (32.f * 7056.f), 800*42*42*64);
    // ---- layer 2: 42x42 (tensor core) ----
    k_conv64_mma<<<dim3(36, 800), 128>>>(p1, cv, k2, b2, 42, 6);
    k_stats<<<dim3(64, 25), 256>>>(cv, 42 * 42);
    k_sreduce<<<7, 256>>>();
    k_bnpool<<<(800*21*21*64 + 255) / 256, 256>>>(cv, p2, g2, be2, 42, 21,
                                                  1.f / (32.f * 1764.f), 800*21*21*64);
    // ---- layer 3: 21x21 (tensor core) ----
    k_conv64_mma<<<dim3(9, 800), 128>>>(p2, cv, k3, b3, 21, 3);
    k_stats<<<dim3(64, 25), 256>>>(cv, 21 * 21);
    k_sreduce<<<7, 256>>>();
    k_bnpool<<<(800*10*10*64 + 255) / 256, 256>>>(cv, p3, g3, be3, 21, 10,
                                                  1.f / (32.f * 441.f), 800*10*10*64);
    // ---- layer 4: 10x10 (tensor core) ----
    k_conv64_mma<<<dim3(4, 800), 128>>>(p3, cv, k4, b4, 10, 2);
    k_stats<<<dim3(64, 25), 256>>>(cv, 10 * 10);
    k_sreduce<<<7, 256>>>();
    k_bnpool<<<(800*5*5*64 + 255) / 256, 256>>>(cv, em, g4, be4, 10, 5,
                                                1.f / (32.f * 100.f), 800*5*5*64);
    // ---- LSTM input GEMM, BiLSTM, epilogue ----
    k_xw<<<dim3(200, 2), 128>>>(fk, fb, bk, bb);
    k_lstm<<<dim3(5, 2), 128>>>(fr, br);
    k_final<<<1, 192>>>(ysup, yqry, out);
}

// round 15
// speedup vs baseline: 1.9432x; 1.0271x over previous
#include <cuda_runtime.h>
#include <math.h>

// ---------------- static scratch (no allocations allowed) ----------------
__device__ float g_conv[(size_t)800 * 84 * 84 * 64];
__device__ float g_p1[(size_t)800 * 42 * 42 * 64];
__device__ float g_p2[(size_t)800 * 21 * 21 * 64];
__device__ float g_p3[(size_t)800 * 10 * 10 * 64];
__device__ float g_emb[(size_t)800 * 1600];
__device__ float g_xw[(size_t)2 * 800 * 128];
__device__ float g_spart[64 * 25 * 64 * 2];
__device__ float g_stats[25 * 64 * 2];
__device__ float g_outs[(size_t)5 * 21 * 32 * 64];
__device__ float g_wsplit[2 * 576 * 64];   // pre-split tf32 hi/lo weights, permuted cout

__device__ __forceinline__ float sigf(float x) { return 1.f / (1.f + expf(-x)); }

typedef unsigned long long u64;
__device__ __forceinline__ u64 pack_dup(float x) {
    u64 r; asm("mov.b64 %0, {%1, %1};" : "=l"(r) : "f"(x)); return r;
}
__device__ __forceinline__ u64 pack2(float lo, float hi) {
    u64 r; asm("mov.b64 %0, {%1, %2};" : "=l"(r) : "f"(lo), "f"(hi)); return r;
}
__device__ __forceinline__ void fma2(u64& d, u64 a, u64 b) {
    asm("fma.rn.f32x2 %0, %1, %2, %0;" : "+l"(d) : "l"(a), "l"(b));
}

// tf32 helpers
__device__ __forceinline__ unsigned f2tf(float x) {
    unsigned r; asm("cvt.rna.tf32.f32 %0, %1;" : "=r"(r) : "f"(x)); return r;
}
__device__ __forceinline__ void tf32_split(float x, float& hi, float& lo) {
    unsigned h = f2tf(x);
    float hf = __uint_as_float(h);
    unsigned l = f2tf(x - hf);
    hi = hf; lo = __uint_as_float(l);
}
__device__ __forceinline__ void mma_tf32(float c[4], const unsigned a[4], unsigned b0, unsigned b1) {
    asm("mma.sync.aligned.m16n8k8.row.col.f32.tf32.tf32.f32 "
        "{%0,%1,%2,%3},{%4,%5,%6,%7},{%8,%9},{%0,%1,%2,%3};"
        : "+f"(c[0]), "+f"(c[1]), "+f"(c[2]), "+f"(c[3])
        : "r"(a[0]), "r"(a[1]), "r"(a[2]), "r"(a[3]), "r"(b0), "r"(b1));
}

// ---------------- conv1: 3->64, 84x84 SAME (fp32, unchanged) ----------------
__global__ void __launch_bounds__(256, 4)
k_conv1(const float* __restrict__ xs, const float* __restrict__ xq,
        const float* __restrict__ w, const float* __restrict__ bias) {
    __shared__ float s_in[6 * 86 * 3];
    __shared__ float s_w[27 * 64];
    const int tid = threadIdx.x;
    const int im = blockIdx.y;
    const int strip = blockIdx.x;
    const int g = im >> 5, n = im & 31;
    const float* src = (g < 20) ? xs + (size_t)(n * 20 + g) * (84 * 84 * 3)
                                : xq + (size_t)(n * 5 + (g - 20)) * (84 * 84 * 3);

    for (int i = tid; i < 27 * 64; i += 256) s_w[i] = w[i];
    for (int i = tid; i < 6 * 86 * 3; i += 256) {
        int ci = i % 3; int c = (i / 3) % 86; int r = i / (3 * 86);
        int gy = strip * 4 - 1 + r, gx = c - 1;
        float v = 0.f;
        if (gy >= 0 && gy < 84 && gx >= 0 && gx < 84) v = src[(gy * 84 + gx) * 3 + ci];
        s_in[i] = v;
    }
    __syncthreads();

    const int cg = tid & 3;
    const int ppb = tid >> 2;
    u64 b2[8];
#pragma unroll
    for (int jp = 0; jp < 8; ++jp)
        b2[jp] = pack2(bias[cg * 16 + 2 * jp], bias[cg * 16 + 2 * jp + 1]);

    for (int it = 0; it < 3; ++it) {
        int pp = ppb + it * 64;
        if (pp < 168) {
            int prow = pp / 42;
            int col0 = (pp % 42) * 2;
            u64 acc0[8], acc1[8];
#pragma unroll
            for (int jp = 0; jp < 8; ++jp) { acc0[jp] = b2[jp]; acc1[jp] = b2[jp]; }
#pragma unroll
            for (int k = 0; k < 27; ++k) {
                int ky = k / 9, kx = (k % 9) / 3, ci = k % 3;
                u64 a0 = pack_dup(s_in[((prow + ky) * 86 + (col0 + kx)) * 3 + ci]);
                u64 a1 = pack_dup(s_in[((prow + ky) * 86 + (col0 + 1 + kx)) * 3 + ci]);
                const ulonglong2* wp = (const ulonglong2*)&s_w[k * 64 + cg * 16];
                ulonglong2 wA = wp[0], wB = wp[1], wC = wp[2], wD = wp[3];
                fma2(acc0[0], a0, wA.x); fma2(acc1[0], a1, wA.x);
                fma2(acc0[1], a0, wA.y); fma2(acc1[1], a1, wA.y);
                fma2(acc0[2], a0, wB.x); fma2(acc1[2], a1, wB.x);
                fma2(acc0[3], a0, wB.y); fma2(acc1[3], a1, wB.y);
                fma2(acc0[4], a0, wC.x); fma2(acc1[4], a1, wC.x);
                fma2(acc0[5], a0, wC.y); fma2(acc1[5], a1, wC.y);
                fma2(acc0[6], a0, wD.x); fma2(acc1[6], a1, wD.x);
                fma2(acc0[7], a0, wD.y); fma2(acc1[7], a1, wD.y);
            }
            int oy = strip * 4 + prow;
            size_t base = ((size_t)im * 7056 + (size_t)oy * 84 + col0) * 64 + cg * 16;
            ulonglong2* o0 = (ulonglong2*)&g_conv[base];
            o0[0] = make_ulonglong2(acc0[0], acc0[1]);
            o0[1] = make_ulonglong2(acc0[2], acc0[3]);
            o0[2] = make_ulonglong2(acc0[4], acc0[5]);
            o0[3] = make_ulonglong2(acc0[6], acc0[7]);
            ulonglong2* o1 = (ulonglong2*)&g_conv[base + 64];
            o1[0] = make_ulonglong2(acc1[0], acc1[1]);
            o1[1] = make_ulonglong2(acc1[2], acc1[3]);
            o1[2] = make_ulonglong2(acc1[4], acc1[5]);
            o1[3] = make_ulonglong2(acc1[6], acc1[7]);
        }
    }
}

// ---- pre-split+permute weights for one 64->64 layer into g_wsplit ----
// layout: g_wsplit[part*36864 + (cc*72 + k9*8 + ci)*64 + cop], cop=(co&7)*8+(co>>3)
__global__ void k_wsplit(const float* __restrict__ w) {
    int i = blockIdx.x * 256 + threadIdx.x;
    if (i >= 576 * 64) return;
    int co = i & 63, r = i >> 6;          // r = k9*64 + cin
    int k9 = r >> 6, cin = r & 63;
    int cc = cin >> 3, ci = cin & 7;
    int cop = (co & 7) * 8 + (co >> 3);
    float v = w[i];
    float hi, lo; tf32_split(v, hi, lo);
    int dst = (cc * 72 + k9 * 8 + ci) * 64 + cop;
    g_wsplit[dst] = hi;
    g_wsplit[36864 + dst] = lo;
}

// ---------------- conv 64->64 via 3xTF32 mma.sync ----------------
// grid (tiles, 800), 128 threads = 4 warps. Tile 8x8 px x 64 cout.
#define BSTR 68   // padded row stride for permuted B
__global__ void __launch_bounds__(128)
k_conv64_mma(const float* __restrict__ in, float* __restrict__ out,
             const float* __restrict__ bias, int H, int tilesX) {
    __shared__ float s_a[2][100 * 9];        // [hi/lo][(py*10+px)*9 + cin]  7.2KB
    __shared__ float s_b[2][72 * BSTR];      // [hi/lo][(k9*8+cin)*BSTR + cop] 38.3KB
    const int tid = threadIdx.x;
    const int im = blockIdx.y;
    const int tile = blockIdx.x;
    const int tx0 = (tile % tilesX) * 8, ty0 = (tile / tilesX) * 8;
    const int HW = H * H;
    const int warp = tid >> 5, lane = tid & 31;
    const int g = lane >> 2, t = lane & 3;
    const float* imbase = in + (size_t)im * HW * 64;

    float c[8][4];
#pragma unroll
    for (int nt = 0; nt < 8; ++nt) {
        float bv0 = bias[nt * 8 + 2 * t];
        float bv1 = bias[nt * 8 + 2 * t + 1];
        c[nt][0] = bv0; c[nt][1] = bv1; c[nt][2] = bv0; c[nt][3] = bv1;
    }

    const int py1 = 2 * warp;
    const int px1 = g;

    for (int cc = 0; cc < 8; ++cc) {
        __syncthreads();
        // stage activations (10x10 halo, 8 cin) with hi/lo split
        for (int i = tid; i < 800; i += 128) {
            int ci = i & 7, pxlin = i >> 3;
            int r = pxlin / 10, col = pxlin % 10;
            int gy = ty0 + r - 1, gx = tx0 + col - 1;
            float v = 0.f;
            if (gy >= 0 && gy < H && gx >= 0 && gx < H)
                v = imbase[(size_t)(gy * H + gx) * 64 + cc * 8 + ci];
            float hi, lo; tf32_split(v, hi, lo);
            s_a[0][pxlin * 9 + ci] = hi;
            s_a[1][pxlin * 9 + ci] = lo;
        }
        // stage pre-split weights: 2304 float4 copies
        for (int i4 = tid; i4 < 2304; i4 += 128) {
            int part = (i4 >= 1152) ? 1 : 0;
            int j = part ? (i4 - 1152) : i4;
            int row = j >> 4, c4 = (j & 15) * 4;
            float4 v = *(const float4*)&g_wsplit[(size_t)part * 36864 + (size_t)(cc * 72 + row) * 64 + c4];
            *(float4*)&s_b[part][row * BSTR + c4] = v;
        }
        __syncthreads();

#pragma unroll 1
        for (int k9 = 0; k9 < 9; ++k9) {
            int ky = k9 / 3, kx = k9 - 3 * ky;
            int ra = ((py1 + ky) * 10 + px1 + kx) * 9;
            int rb = ((py1 + 1 + ky) * 10 + px1 + kx) * 9;
            unsigned a_hi[4], a_lo[4];
            a_hi[0] = __float_as_uint(s_a[0][ra + t]);
            a_hi[1] = __float_as_uint(s_a[0][rb + t]);
            a_hi[2] = __float_as_uint(s_a[0][ra + t + 4]);
            a_hi[3] = __float_as_uint(s_a[0][rb + t + 4]);
            a_lo[0] = __float_as_uint(s_a[1][ra + t]);
            a_lo[1] = __float_as_uint(s_a[1][rb + t]);
            a_lo[2] = __float_as_uint(s_a[1][ra + t + 4]);
            a_lo[3] = __float_as_uint(s_a[1][rb + t + 4]);

            int wr0 = (k9 * 8 + t) * BSTR + g * 8;
            int wr1 = (k9 * 8 + t + 4) * BSTR + g * 8;
            float4 h0a = *(const float4*)&s_b[0][wr0];
            float4 h0b = *(const float4*)&s_b[0][wr0 + 4];
            float4 h1a = *(const float4*)&s_b[0][wr1];
            float4 h1b = *(const float4*)&s_b[0][wr1 + 4];
            float4 l0a = *(const float4*)&s_b[1][wr0];
            float4 l0b = *(const float4*)&s_b[1][wr0 + 4];
            float4 l1a = *(const float4*)&s_b[1][wr1];
            float4 l1b = *(const float4*)&s_b[1][wr1 + 4];
            float bh0v[8] = {h0a.x, h0a.y, h0a.z, h0a.w, h0b.x, h0b.y, h0b.z, h0b.w};
            float bh1v[8] = {h1a.x, h1a.y, h1a.z, h1a.w, h1b.x, h1b.y, h1b.z, h1b.w};
            float bl0v[8] = {l0a.x, l0a.y, l0a.z, l0a.w, l0b.x, l0b.y, l0b.z, l0b.w};
            float bl1v[8] = {l1a.x, l1a.y, l1a.z, l1a.w, l1b.x, l1b.y, l1b.z, l1b.w};
#pragma unroll
            for (int nt = 0; nt < 8; ++nt) {
                unsigned bh0 = __float_as_uint(bh0v[nt]);
                unsigned bh1 = __float_as_uint(bh1v[nt]);
                unsigned bl0 = __float_as_uint(bl0v[nt]);
                unsigned bl1 = __float_as_uint(bl1v[nt]);
                mma_tf32(c[nt], a_hi, bh0, bh1);   // hi*hi
                mma_tf32(c[nt], a_lo, bh0, bh1);   // lo*hi
                mma_tf32(c[nt], a_hi, bl0, bl1);   // hi*lo
            }
        }
    }

    // epilogue: write 16px x 64cout per warp
    int ox = tx0 + px1;
    int oy1 = ty0 + py1;
    int oy2 = oy1 + 1;
    if (ox < H) {
        if (oy1 < H) {
            float* o = &out[((size_t)im * HW + (size_t)oy1 * H + ox) * 64];
#pragma unroll
            for (int nt = 0; nt < 8; ++nt)
                *(float2*)&o[nt * 8 + 2 * t] = make_float2(c[nt][0], c[nt][1]);
        }
        if (oy2 < H) {
            float* o = &out[((size_t)im * HW + (size_t)oy2 * H + ox) * 64];
#pragma unroll
            for (int nt = 0; nt < 8; ++nt)
                *(float2*)&o[nt * 8 + 2 * t] = make_float2(c[nt][2], c[nt][3]);
        }
    }
}

// stats pass 1: per-block partials. grid (64, 25 groups), 256 threads.
__global__ void k_stats(const float* __restrict__ conv, int HW) {
    __shared__ float ss[256], sq[256];
    int g = blockIdx.y, blk = blockIdx.x, tid = threadIdx.x;
    int c = tid & 63, l = tid >> 6;
    int P = 32 * HW;
    float s = 0.f, q = 0.f;
    for (int p = blk * 4 + l; p < P; p += 64 * 4) {
        float v = conv[((size_t)g * P + p) * 64 + c];
        s += v; q += v * v;
    }
    ss[tid] = s; sq[tid] = q;
    __syncthreads();
    if (tid < 64) {
        s = ss[tid] + ss[tid + 64] + ss[tid + 128] + ss[tid + 192];
        q = sq[tid] + sq[tid + 64] + sq[tid + 128] + sq[tid + 192];
        g_spart[((size_t)blk * 25 + g) * 128 + tid * 2]     = s;
        g_spart[((size_t)blk * 25 + g) * 128 + tid * 2 + 1] = q;
    }
}

__global__ void k_sreduce() {
    int i = blockIdx.x * 256 + threadIdx.x;
    if (i >= 1600) return;
    int g = i >> 6, c = i & 63;
    float s = 0.f, q = 0.f;
#pragma unroll 4
    for (int blk = 0; blk < 64; ++blk) {
        s += g_spart[((size_t)blk * 25 + g) * 128 + c * 2];
        q += g_spart[((size_t)blk * 25 + g) * 128 + c * 2 + 1];
    }
    g_stats[i * 2] = s;
    g_stats[i * 2 + 1] = q;
}

__global__ void k_bnpool(const float* __restrict__ conv, float* __restrict__ out,
                         const float* __restrict__ gam, const float* __restrict__ bet,
                         int Hin, int Hout, float invcnt, int total) {
    int i = blockIdx.x * 256 + threadIdx.x;
    if (i >= total) return;
    int c = i & 63;
    int t = i >> 6;
    int xo = t % Hout; t /= Hout;
    int yo = t % Hout;
    int im = t / Hout;
    int g = im >> 5;
    float s = g_stats[(g * 64 + c) * 2];
    float qq = g_stats[(g * 64 + c) * 2 + 1];
    float mean = s * invcnt;
    float var = qq * invcnt - mean * mean;
    float scale = gam[c] * rsqrtf(var + 1e-3f);
    float shift = bet[c] - mean * scale;
    size_t base = (((size_t)im * Hin + 2 * yo) * Hin + 2 * xo) * 64 + c;
    float v00 = fmaxf(conv[base] * scale + shift, 0.f);
    float v01 = fmaxf(conv[base + 64] * scale + shift, 0.f);
    float v10 = fmaxf(conv[base + (size_t)Hin * 64] * scale + shift, 0.f);
    float v11 = fmaxf(conv[base + (size_t)Hin * 64 + 64] * scale + shift, 0.f);
    out[i] = fmaxf(fmaxf(v00, v01), fmaxf(v10, v11));
}

__global__ void k_xw(const float* __restrict__ fk, const float* __restrict__ fb,
                     const float* __restrict__ bk, const float* __restrict__ bb) {
    __shared__ float es[4 * 1600];
    int tid = threadIdx.x, dir = blockIdx.y, im0 = blockIdx.x * 4;
    const float* W = dir ? bk : fk;
    const float* B = dir ? bb : fb;
    for (int i = tid; i < 6400; i += 128) es[i] = g_emb[(size_t)im0 * 1600 + i];
    __syncthreads();
    float a0 = 0.f, a1 = 0.f, a2 = 0.f, a3 = 0.f;
#pragma unroll 4
    for (int k = 0; k < 1600; ++k) {
        float wv = W[(size_t)k * 128 + tid];
        a0 += es[k] * wv;
        a1 += es[1600 + k] * wv;
        a2 += es[3200 + k] * wv;
        a3 += es[4800 + k] * wv;
    }
    float bv = B[tid];
    g_xw[((size_t)dir * 800 + im0 + 0) * 128 + tid] = a0 + bv;
    g_xw[((size_t)dir * 800 + im0 + 1) * 128 + tid] = a1 + bv;
    g_xw[((size_t)dir * 800 + im0 + 2) * 128 + tid] = a2 + bv;
    g_xw[((size_t)dir * 800 + im0 + 3) * 128 + tid] = a3 + bv;
}

__global__ void k_lstm(const float* __restrict__ fr, const float* __restrict__ br) {
    __shared__ float wh[32 * 128];
    __shared__ float hs[672], cs[672], zs[21 * 128];
    int q = blockIdx.x, dir = blockIdx.y, tid = threadIdx.x;
    const float* R = dir ? br : fr;
    for (int i = tid; i < 4096; i += 128) wh[i] = R[i];
    for (int i = tid; i < 672; i += 128) { hs[i] = 0.f; cs[i] = 0.f; }
    __syncthreads();

    for (int t = 0; t < 32; ++t) {
        int e = dir ? 31 - t : t;
#pragma unroll 3
        for (int j = 0; j < 21; ++j) {
            int gj = (j < 20) ? j : 20 + q;
            float z = g_xw[((size_t)dir * 800 + gj * 32 + e) * 128 + tid];
            float z1 = 0.f;
#pragma unroll
            for (int k = 0; k < 32; k += 2) {
                z  += hs[j * 32 + k]     * wh[k * 128 + tid];
                z1 += hs[j * 32 + k + 1] * wh[(k + 1) * 128 + tid];
            }
            zs[j * 128 + tid] = z + z1;
        }
        __syncthreads();
        for (int idx = tid; idx < 672; idx += 128) {
            int j = idx >> 5, u = idx & 31;
            float zi = zs[j * 128 + u];
            float zf = zs[j * 128 + 32 + u];
            float zg = zs[j * 128 + 64 + u];
            float zo = zs[j * 128 + 96 + u];
            float c = sigf(zf) * cs[idx] + sigf(zi) * tanhf(zg);
            float h = sigf(zo) * tanhf(c);
            cs[idx] = c; hs[idx] = h;
            g_outs[(((size_t)q * 21 + j) * 32 + e) * 64 + dir * 32 + u] = h;
        }
        __syncthreads();
    }
}

__global__ void k_final(const int* __restrict__ ys, const int* __restrict__ yq,
                        float* __restrict__ out) {
    __shared__ float s_ce[160];
    __shared__ float s_eq[160];
    int t = threadIdx.x;
    if (t < 160) {
        int q = t / 32, b = t % 32;
        const float* qp = &g_outs[(((size_t)q * 21 + 20) * 32 + b) * 64];
        float val[20];
        for (int s = 0; s < 20; ++s) {
            const float* sp = &g_outs[(((size_t)q * 21 + s) * 32 + b) * 64];
            float dot = 0.f, ssq = 0.f;
            for (int d = 0; d < 64; ++d) {
                float sv = sp[d];
                dot += qp[d] * sv;
                ssq += sv * sv;
            }
            val[s] = dot * rsqrtf(fmaxf(ssq, 1e-10f));
        }
        float m = -1e30f;
        for (int s = 0; s < 20; ++s) m = fmaxf(m, val[s]);
        float sum = 0.f;
        for (int s = 0; s < 20; ++s) { val[s] = expf(val[s] - m); sum += val[s]; }
        float inv = 1.f / sum;

        float preds[20];
        for (int w = 0; w < 20; ++w) preds[w] = 0.f;
        for (int s = 0; s < 20; ++s) preds[ys[b * 20 + s]] += val[s] * inv;

        int lbl = yq[b * 5 + q];
        float p = fminf(fmaxf(preds[lbl], 1e-7f), 1.f - 1e-7f);
        s_ce[t] = -logf(p);

        int am = 0; float bv = preds[0];
        for (int w = 1; w < 20; ++w) if (preds[w] > bv) { bv = preds[w]; am = w; }
        s_eq[t] = (am == lbl) ? 1.f : 0.f;
    }
    __syncthreads();
    if (t < 32) {
        float ce = 0.f;
        for (int q = 0; q < 5; ++q) ce += s_ce[q * 32 + t];
        out[t] = ce * 0.2f;
    }
    if (t == 32) {
        float a = 0.f;
        for (int i = 0; i < 160; ++i) a += s_eq[i];
        out[32] = a * (1.f / 160.f);
    }
}

extern "C" void kernel_launch(void* const* d_in, const int* in_sizes, int n_in,
                              void* d_out, int out_size) {
    const float* xs  = (const float*)d_in[0];
    const int*   ysup= (const int*)  d_in[1];
    const float* xq  = (const float*)d_in[2];
    const int*   yqry= (const int*)  d_in[3];
    const float* k1 = (const float*)d_in[4];
    const float* b1 = (const float*)d_in[5];
    const float* g1 = (const float*)d_in[6];
    const float* be1= (const float*)d_in[7];
    const float* k2 = (const float*)d_in[8];
    const float* b2 = (const float*)d_in[9];
    const float* g2 = (const float*)d_in[10];
    const float* be2= (const float*)d_in[11];
    const float* k3 = (const float*)d_in[12];
    const float* b3 = (const float*)d_in[13];
    const float* g3 = (const float*)d_in[14];
    const float* be3= (const float*)d_in[15];
    const float* k4 = (const float*)d_in[16];
    const float* b4 = (const float*)d_in[17];
    const float* g4 = (const float*)d_in[18];
    const float* be4= (const float*)d_in[19];
    const float* fk = (const float*)d_in[20];
    const float* fr = (const float*)d_in[21];
    const float* fb = (const float*)d_in[22];
    const float* bk = (const float*)d_in[23];
    const float* br = (const float*)d_in[24];
    const float* bb = (const float*)d_in[25];
    float* out = (float*)d_out;

    float* cv; cudaGetSymbolAddress((void**)&cv, g_conv);
    float* p1; cudaGetSymbolAddress((void**)&p1, g_p1);
    float* p2; cudaGetSymbolAddress((void**)&p2, g_p2);
    float* p3; cudaGetSymbolAddress((void**)&p3, g_p3);
    float* em; cudaGetSymbolAddress((void**)&em, g_emb);

    // ---- layer 1: 84x84, 3->64 ----
    k_conv1<<<dim3(21, 800), 256>>>(xs, xq, k1, b1);
    k_stats<<<dim3(64, 25), 256>>>(cv, 84 * 84);
    k_sreduce<<<7, 256>>>();
    k_bnpool<<<(800*42*42*64 + 255) / 256, 256>>>(cv, p1, g1, be1, 84, 42,
                                                  1.f / (32.f * 7056.f), 800*42*42*64);
    // ---- layer 2: 42x42 (tensor core) ----
    k_wsplit<<<144, 256>>>(k2);
    k_conv64_mma<<<dim3(36, 800), 128>>>(p1, cv, b2, 42, 6);
    k_stats<<<dim3(64, 25), 256>>>(cv, 42 * 42);
    k_sreduce<<<7, 256>>>();
    k_bnpool<<<(800*21*21*64 + 255) / 256, 256>>>(cv, p2, g2, be2, 42, 21,
                                                  1.f / (32.f * 1764.f), 800*21*21*64);
    // ---- layer 3: 21x21 (tensor core) ----
    k_wsplit<<<144, 256>>>(k3);
    k_conv64_mma<<<dim3(9, 800), 128>>>(p2, cv, b3, 21, 3);
    k_stats<<<dim3(64, 25), 256>>>(cv, 21 * 21);
    k_sreduce<<<7, 256>>>();
    k_bnpool<<<(800*10*10*64 + 255) / 256, 256>>>(cv, p3, g3, be3, 21, 10,
                                                  1.f / (32.f * 441.f), 800*10*10*64);
    // ---- layer 4: 10x10 (tensor core) ----
    k_wsplit<<<144, 256>>>(k4);
    k_conv64_mma<<<dim3(4, 800), 128>>>(p3, cv, b4, 10, 2);
    k_stats<<<dim3(64, 25), 256>>>(cv, 10 * 10);
    k_sreduce<<<7, 256>>>();
    k_bnpool<<<(800*5*5*64 + 255) / 256, 256>>>(cv, em, g4, be4, 10, 5,
                                                1.f / (32.f * 100.f), 800*5*5*64);
    // ---- LSTM input GEMM, BiLSTM, epilogue ----
    k_xw<<<dim3(200, 2), 128>>>(fk, fb, bk, bb);
    k_lstm<<<dim3(5, 2), 128>>>(fr, br);
    k_final<<<1, 192>>>(ysup, yqry, out);
}

// round 17
// speedup vs baseline: 2.8633x; 1.4735x over previous
#include <cuda_runtime.h>
#include <cuda_fp16.h>
#include <math.h>

// ---------------- static scratch (no allocations allowed) ----------------
__device__ float g_conv[(size_t)800 * 84 * 84 * 64];
__device__ float g_p1[(size_t)800 * 42 * 42 * 64];
__device__ float g_p2[(size_t)800 * 21 * 21 * 64];
__device__ float g_p3[(size_t)800 * 10 * 10 * 64];
__device__ float g_emb[(size_t)800 * 1600];
__device__ float g_xw[(size_t)2 * 800 * 128];
__device__ float g_spart[64 * 25 * 64 * 2];
__device__ float g_stats[25 * 64 * 2];
__device__ float g_outs[(size_t)5 * 21 * 32 * 64];
__device__ unsigned g_wh[(size_t)2 * 18432];   // fp16 hi/lo split weights (half2 words)

__device__ __forceinline__ float sigf(float x) { return 1.f / (1.f + expf(-x)); }

typedef unsigned long long u64;
__device__ __forceinline__ u64 pack_dup(float x) {
    u64 r; asm("mov.b64 %0, {%1, %1};" : "=l"(r) : "f"(x)); return r;
}
__device__ __forceinline__ u64 pack2(float lo, float hi) {
    u64 r; asm("mov.b64 %0, {%1, %2};" : "=l"(r) : "f"(lo), "f"(hi)); return r;
}
__device__ __forceinline__ void fma2(u64& d, u64 a, u64 b) {
    asm("fma.rn.f32x2 %0, %1, %2, %0;" : "+l"(d) : "l"(a), "l"(b));
}

// f16 MMA m16n8k16, fp32 accumulate
__device__ __forceinline__ void mma_f16(float c[4], const unsigned a[4], unsigned b0, unsigned b1) {
    asm("mma.sync.aligned.m16n8k16.row.col.f32.f16.f16.f32 "
        "{%0,%1,%2,%3},{%4,%5,%6,%7},{%8,%9},{%0,%1,%2,%3};"
        : "+f"(c[0]), "+f"(c[1]), "+f"(c[2]), "+f"(c[3])
        : "r"(a[0]), "r"(a[1]), "r"(a[2]), "r"(a[3]), "r"(b0), "r"(b1));
}

// ---------------- conv1: 3->64, 84x84 SAME (fp32, unchanged) ----------------
__global__ void __launch_bounds__(256, 4)
k_conv1(const float* __restrict__ xs, const float* __restrict__ xq,
        const float* __restrict__ w, const float* __restrict__ bias) {
    __shared__ float s_in[6 * 86 * 3];
    __shared__ float s_w[27 * 64];
    const int tid = threadIdx.x;
    const int im = blockIdx.y;
    const int strip = blockIdx.x;
    const int g = im >> 5, n = im & 31;
    const float* src = (g < 20) ? xs + (size_t)(n * 20 + g) * (84 * 84 * 3)
                                : xq + (size_t)(n * 5 + (g - 20)) * (84 * 84 * 3);

    for (int i = tid; i < 27 * 64; i += 256) s_w[i] = w[i];
    for (int i = tid; i < 6 * 86 * 3; i += 256) {
        int ci = i % 3; int c = (i / 3) % 86; int r = i / (3 * 86);
        int gy = strip * 4 - 1 + r, gx = c - 1;
        float v = 0.f;
        if (gy >= 0 && gy < 84 && gx >= 0 && gx < 84) v = src[(gy * 84 + gx) * 3 + ci];
        s_in[i] = v;
    }
    __syncthreads();

    const int cg = tid & 3;
    const int ppb = tid >> 2;
    u64 b2[8];
#pragma unroll
    for (int jp = 0; jp < 8; ++jp)
        b2[jp] = pack2(bias[cg * 16 + 2 * jp], bias[cg * 16 + 2 * jp + 1]);

    for (int it = 0; it < 3; ++it) {
        int pp = ppb + it * 64;
        if (pp < 168) {
            int prow = pp / 42;
            int col0 = (pp % 42) * 2;
            u64 acc0[8], acc1[8];
#pragma unroll
            for (int jp = 0; jp < 8; ++jp) { acc0[jp] = b2[jp]; acc1[jp] = b2[jp]; }
#pragma unroll
            for (int k = 0; k < 27; ++k) {
                int ky = k / 9, kx = (k % 9) / 3, ci = k % 3;
                u64 a0 = pack_dup(s_in[((prow + ky) * 86 + (col0 + kx)) * 3 + ci]);
                u64 a1 = pack_dup(s_in[((prow + ky) * 86 + (col0 + 1 + kx)) * 3 + ci]);
                const ulonglong2* wp = (const ulonglong2*)&s_w[k * 64 + cg * 16];
                ulonglong2 wA = wp[0], wB = wp[1], wC = wp[2], wD = wp[3];
                fma2(acc0[0], a0, wA.x); fma2(acc1[0], a1, wA.x);
                fma2(acc0[1], a0, wA.y); fma2(acc1[1], a1, wA.y);
                fma2(acc0[2], a0, wB.x); fma2(acc1[2], a1, wB.x);
                fma2(acc0[3], a0, wB.y); fma2(acc1[3], a1, wB.y);
                fma2(acc0[4], a0, wC.x); fma2(acc1[4], a1, wC.x);
                fma2(acc0[5], a0, wC.y); fma2(acc1[5], a1, wC.y);
                fma2(acc0[6], a0, wD.x); fma2(acc1[6], a1, wD.x);
                fma2(acc0[7], a0, wD.y); fma2(acc1[7], a1, wD.y);
            }
            int oy = strip * 4 + prow;
            size_t base = ((size_t)im * 7056 + (size_t)oy * 84 + col0) * 64 + cg * 16;
            ulonglong2* o0 = (ulonglong2*)&g_conv[base];
            o0[0] = make_ulonglong2(acc0[0], acc0[1]);
            o0[1] = make_ulonglong2(acc0[2], acc0[3]);
            o0[2] = make_ulonglong2(acc0[4], acc0[5]);
            o0[3] = make_ulonglong2(acc0[6], acc0[7]);
            ulonglong2* o1 = (ulonglong2*)&g_conv[base + 64];
            o1[0] = make_ulonglong2(acc1[0], acc1[1]);
            o1[1] = make_ulonglong2(acc1[2], acc1[3]);
            o1[2] = make_ulonglong2(acc1[4], acc1[5]);
            o1[3] = make_ulonglong2(acc1[6], acc1[7]);
        }
    }
}

// ---- pre-split weights to fp16 hi/lo, permuted, half2-packed by cin pairs ----
// dst half idx: (((cc*9 + k9)*8 + kp)*64 + cop)*2 + par ; cin = cc*16 + kp*2 + par
__global__ void k_wsplit_h(const float* __restrict__ w) {
    int i = blockIdx.x * 256 + threadIdx.x;
    if (i >= 576 * 64) return;
    int co = i & 63, r = i >> 6;          // r = k9*64 + cin
    int k9 = r >> 6, cin = r & 63;
    int cc = cin >> 4, kp = (cin >> 1) & 7, par = cin & 1;
    int cop = (co & 7) * 8 + (co >> 3);
    float v = w[i];
    __half h = __float2half_rn(v);
    __half l = __float2half_rn(v - __half2float(h));
    size_t dst = ((((size_t)cc * 9 + k9) * 8 + kp) * 64 + cop) * 2 + par;
    ((__half*)g_wh)[dst] = h;
    ((__half*)g_wh)[36864 + dst] = l;
}

// ---------------- conv 64->64 via 3xFP16 mma.sync m16n8k16 ----------------
// grid (tiles, 800), 128 threads = 4 warps. Tile 8x8 px x 64 cout.
#define BS2 68   // padded row stride (u32 half2 words)
__global__ void __launch_bounds__(128)
k_conv64_mma(const float* __restrict__ in, float* __restrict__ out,
             const float* __restrict__ bias, int H, int tilesX) {
    __shared__ unsigned s_a[2][100 * 8];     // [hi/lo][pixel*8 + kpair]  3.2KB each
    __shared__ unsigned s_b[2][72 * BS2];    // [hi/lo][(k9*8+kp)*BS2 + cop] 19.6KB each
    const int tid = threadIdx.x;
    const int im = blockIdx.y;
    const int tile = blockIdx.x;
    const int tx0 = (tile % tilesX) * 8, ty0 = (tile / tilesX) * 8;
    const int HW = H * H;
    const int warp = tid >> 5, lane = tid & 31;
    const int g = lane >> 2, t = lane & 3;
    const float* imbase = in + (size_t)im * HW * 64;

    float c[8][4];
#pragma unroll
    for (int nt = 0; nt < 8; ++nt) {
        float bv0 = bias[nt * 8 + 2 * t];
        float bv1 = bias[nt * 8 + 2 * t + 1];
        c[nt][0] = bv0; c[nt][1] = bv1; c[nt][2] = bv0; c[nt][3] = bv1;
    }

    const int py1 = 2 * warp;
    const int px1 = g;

    for (int cc = 0; cc < 4; ++cc) {
        __syncthreads();
        // stage activations (10x10 halo, 16 cin) split to fp16 hi/lo halves
        for (int i = tid; i < 1600; i += 128) {
            int ci = i & 15, pxlin = i >> 4;
            int r = pxlin / 10, col = pxlin % 10;
            int gy = ty0 + r - 1, gx = tx0 + col - 1;
            float v = 0.f;
            if (gy >= 0 && gy < H && gx >= 0 && gx < H)
                v = imbase[(size_t)(gy * H + gx) * 64 + cc * 16 + ci];
            __half h = __float2half_rn(v);
            __half l = __float2half_rn(v - __half2float(h));
            ((__half*)s_a[0])[pxlin * 16 + ci] = h;
            ((__half*)s_a[1])[pxlin * 16 + ci] = l;
        }
        // stage pre-split weights: 2*72*16 uint4 copies
        for (int i4 = tid; i4 < 2304; i4 += 128) {
            int part = (i4 >= 1152) ? 1 : 0;
            int j = part ? (i4 - 1152) : i4;
            int row = j >> 4, q = (j & 15) * 4;
            uint4 v = *(const uint4*)&g_wh[(size_t)part * 18432 + ((size_t)cc * 72 + row) * 64 + q];
            *(uint4*)&s_b[part][row * BS2 + q] = v;
        }
        __syncthreads();

#pragma unroll 1
        for (int k9 = 0; k9 < 9; ++k9) {
            int ky = k9 / 3, kx = k9 - 3 * ky;
            int ra8 = ((py1 + ky) * 10 + px1 + kx) * 8;
            int rb8 = ((py1 + 1 + ky) * 10 + px1 + kx) * 8;
            unsigned a_hi[4], a_lo[4];
            a_hi[0] = s_a[0][ra8 + t];
            a_hi[1] = s_a[0][rb8 + t];
            a_hi[2] = s_a[0][ra8 + t + 4];
            a_hi[3] = s_a[0][rb8 + t + 4];
            a_lo[0] = s_a[1][ra8 + t];
            a_lo[1] = s_a[1][rb8 + t];
            a_lo[2] = s_a[1][ra8 + t + 4];
            a_lo[3] = s_a[1][rb8 + t + 4];

            int wr0 = (k9 * 8 + t) * BS2 + g * 8;
            int wr1 = (k9 * 8 + t + 4) * BS2 + g * 8;
            uint4 H0a = *(const uint4*)&s_b[0][wr0];
            uint4 H0b = *(const uint4*)&s_b[0][wr0 + 4];
            uint4 H1a = *(const uint4*)&s_b[0][wr1];
            uint4 H1b = *(const uint4*)&s_b[0][wr1 + 4];
            uint4 L0a = *(const uint4*)&s_b[1][wr0];
            uint4 L0b = *(const uint4*)&s_b[1][wr0 + 4];
            uint4 L1a = *(const uint4*)&s_b[1][wr1];
            uint4 L1b = *(const uint4*)&s_b[1][wr1 + 4];
            unsigned bh0v[8] = {H0a.x, H0a.y, H0a.z, H0a.w, H0b.x, H0b.y, H0b.z, H0b.w};
            unsigned bh1v[8] = {H1a.x, H1a.y, H1a.z, H1a.w, H1b.x, H1b.y, H1b.z, H1b.w};
            unsigned bl0v[8] = {L0a.x, L0a.y, L0a.z, L0a.w, L0b.x, L0b.y, L0b.z, L0b.w};
            unsigned bl1v[8] = {L1a.x, L1a.y, L1a.z, L1a.w, L1b.x, L1b.y, L1b.z, L1b.w};
#pragma unroll
            for (int nt = 0; nt < 8; ++nt) {
                mma_f16(c[nt], a_hi, bh0v[nt], bh1v[nt]);   // hi*hi
                mma_f16(c[nt], a_lo, bh0v[nt], bh1v[nt]);   // lo*hi
                mma_f16(c[nt], a_hi, bl0v[nt], bl1v[nt]);   // hi*lo
            }
        }
    }

    // epilogue: write 16px x 64cout per warp
    int ox = tx0 + px1;
    int oy1 = ty0 + py1;
    int oy2 = oy1 + 1;
    if (ox < H) {
        if (oy1 < H) {
            float* o = &out[((size_t)im * HW + (size_t)oy1 * H + ox) * 64];
#pragma unroll
            for (int nt = 0; nt < 8; ++nt)
                *(float2*)&o[nt * 8 + 2 * t] = make_float2(c[nt][0], c[nt][1]);
        }
        if (oy2 < H) {
            float* o = &out[((size_t)im * HW + (size_t)oy2 * H + ox) * 64];
#pragma unroll
            for (int nt = 0; nt < 8; ++nt)
                *(float2*)&o[nt * 8 + 2 * t] = make_float2(c[nt][2], c[nt][3]);
        }
    }
}

// stats pass 1: per-block partials. grid (64, 25 groups), 256 threads.
__global__ void k_stats(const float* __restrict__ conv, int HW) {
    __shared__ float ss[256], sq[256];
    int g = blockIdx.y, blk = blockIdx.x, tid = threadIdx.x;
    int c = tid & 63, l = tid >> 6;
    int P = 32 * HW;
    float s = 0.f, q = 0.f;
    for (int p = blk * 4 + l; p < P; p += 64 * 4) {
        float v = conv[((size_t)g * P + p) * 64 + c];
        s += v; q += v * v;
    }
    ss[tid] = s; sq[tid] = q;
    __syncthreads();
    if (tid < 64) {
        s = ss[tid] + ss[tid + 64] + ss[tid + 128] + ss[tid + 192];
        q = sq[tid] + sq[tid + 64] + sq[tid + 128] + sq[tid + 192];
        g_spart[((size_t)blk * 25 + g) * 128 + tid * 2]     = s;
        g_spart[((size_t)blk * 25 + g) * 128 + tid * 2 + 1] = q;
    }
}

__global__ void k_sreduce() {
    int i = blockIdx.x * 256 + threadIdx.x;
    if (i >= 1600) return;
    int g = i >> 6, c = i & 63;
    float s = 0.f, q = 0.f;
#pragma unroll 4
    for (int blk = 0; blk < 64; ++blk) {
        s += g_spart[((size_t)blk * 25 + g) * 128 + c * 2];
        q += g_spart[((size_t)blk * 25 + g) * 128 + c * 2 + 1];
    }
    g_stats[i * 2] = s;
    g_stats[i * 2 + 1] = q;
}

__global__ void k_bnpool(const float* __restrict__ conv, float* __restrict__ out,
                         const float* __restrict__ gam, const float* __restrict__ bet,
                         int Hin, int Hout, float invcnt, int total) {
    int i = blockIdx.x * 256 + threadIdx.x;
    if (i >= total) return;
    int c = i & 63;
    int t = i >> 6;
    int xo = t % Hout; t /= Hout;
    int yo = t % Hout;
    int im = t / Hout;
    int g = im >> 5;
    float s = g_stats[(g * 64 + c) * 2];
    float qq = g_stats[(g * 64 + c) * 2 + 1];
    float mean = s * invcnt;
    float var = qq * invcnt - mean * mean;
    float scale = gam[c] * rsqrtf(var + 1e-3f);
    float shift = bet[c] - mean * scale;
    size_t base = (((size_t)im * Hin + 2 * yo) * Hin + 2 * xo) * 64 + c;
    float v00 = fmaxf(conv[base] * scale + shift, 0.f);
    float v01 = fmaxf(conv[base + 64] * scale + shift, 0.f);
    float v10 = fmaxf(conv[base + (size_t)Hin * 64] * scale + shift, 0.f);
    float v11 = fmaxf(conv[base + (size_t)Hin * 64 + 64] * scale + shift, 0.f);
    out[i] = fmaxf(fmaxf(v00, v01), fmaxf(v10, v11));
}

__global__ void k_xw(const float* __restrict__ fk, const float* __restrict__ fb,
                     const float* __restrict__ bk, const float* __restrict__ bb) {
    __shared__ float es[4 * 1600];
    int tid = threadIdx.x, dir = blockIdx.y, im0 = blockIdx.x * 4;
    const float* W = dir ? bk : fk;
    const float* B = dir ? bb : fb;
    for (int i = tid; i < 6400; i += 128) es[i] = g_emb[(size_t)im0 * 1600 + i];
    __syncthreads();
    float a0 = 0.f, a1 = 0.f, a2 = 0.f, a3 = 0.f;
#pragma unroll 4
    for (int k = 0; k < 1600; ++k) {
        float wv = W[(size_t)k * 128 + tid];
        a0 += es[k] * wv;
        a1 += es[1600 + k] * wv;
        a2 += es[3200 + k] * wv;
        a3 += es[4800 + k] * wv;
    }
    float bv = B[tid];
    g_xw[((size_t)dir * 800 + im0 + 0) * 128 + tid] = a0 + bv;
    g_xw[((size_t)dir * 800 + im0 + 1) * 128 + tid] = a1 + bv;
    g_xw[((size_t)dir * 800 + im0 + 2) * 128 + tid] = a2 + bv;
    g_xw[((size_t)dir * 800 + im0 + 3) * 128 + tid] = a3 + bv;
}

__global__ void k_lstm(const float* __restrict__ fr, const float* __restrict__ br) {
    __shared__ float wh[32 * 128];
    __shared__ float hs[672], cs[672], zs[21 * 128];
    int q = blockIdx.x, dir = blockIdx.y, tid = threadIdx.x;
    const float* R = dir ? br : fr;
    for (int i = tid; i < 4096; i += 128) wh[i] = R[i];
    for (int i = tid; i < 672; i += 128) { hs[i] = 0.f; cs[i] = 0.f; }
    __syncthreads();

    for (int t = 0; t < 32; ++t) {
        int e = dir ? 31 - t : t;
#pragma unroll 3
        for (int j = 0; j < 21; ++j) {
            int gj = (j < 20) ? j : 20 + q;
            float z = g_xw[((size_t)dir * 800 + gj * 32 + e) * 128 + tid];
            float z1 = 0.f;
#pragma unroll
            for (int k = 0; k < 32; k += 2) {
                z  += hs[j * 32 + k]     * wh[k * 128 + tid];
                z1 += hs[j * 32 + k + 1] * wh[(k + 1) * 128 + tid];
            }
            zs[j * 128 + tid] = z + z1;
        }
        __syncthreads();
        for (int idx = tid; idx < 672; idx += 128) {
            int j = idx >> 5, u = idx & 31;
            float zi = zs[j * 128 + u];
            float zf = zs[j * 128 + 32 + u];
            float zg = zs[j * 128 + 64 + u];
            float zo = zs[j * 128 + 96 + u];
            float c = sigf(zf) * cs[idx] + sigf(zi) * tanhf(zg);
            float h = sigf(zo) * tanhf(c);
            cs[idx] = c; hs[idx] = h;
            g_outs[(((size_t)q * 21 + j) * 32 + e) * 64 + dir * 32 + u] = h;
        }
        __syncthreads();
    }
}

__global__ void k_final(const int* __restrict__ ys, const int* __restrict__ yq,
                        float* __restrict__ out) {
    __shared__ float s_ce[160];
    __shared__ float s_eq[160];
    int t = threadIdx.x;
    if (t < 160) {
        int q = t / 32, b = t % 32;
        const float* qp = &g_outs[(((size_t)q * 21 + 20) * 32 + b) * 64];
        float val[20];
        for (int s = 0; s < 20; ++s) {
            const float* sp = &g_outs[(((size_t)q * 21 + s) * 32 + b) * 64];
            float dot = 0.f, ssq = 0.f;
            for (int d = 0; d < 64; ++d) {
                float sv = sp[d];
                dot += qp[d] * sv;
                ssq += sv * sv;
            }
            val[s] = dot * rsqrtf(fmaxf(ssq, 1e-10f));
        }
        float m = -1e30f;
        for (int s = 0; s < 20; ++s) m = fmaxf(m, val[s]);
        float sum = 0.f;
        for (int s = 0; s < 20; ++s) { val[s] = expf(val[s] - m); sum += val[s]; }
        float inv = 1.f / sum;

        float preds[20];
        for (int w = 0; w < 20; ++w) preds[w] = 0.f;
        for (int s = 0; s < 20; ++s) preds[ys[b * 20 + s]] += val[s] * inv;

        int lbl = yq[b * 5 + q];
        float p = fminf(fmaxf(preds[lbl], 1e-7f), 1.f - 1e-7f);
        s_ce[t] = -logf(p);

        int am = 0; float bv = preds[0];
        for (int w = 1; w < 20; ++w) if (preds[w] > bv) { bv = preds[w]; am = w; }
        s_eq[t] = (am == lbl) ? 1.f : 0.f;
    }
    __syncthreads();
    if (t < 32) {
        float ce = 0.f;
        for (int q = 0; q < 5; ++q) ce += s_ce[q * 32 + t];
        out[t] = ce * 0.2f;
    }
    if (t == 32) {
        float a = 0.f;
        for (int i = 0; i < 160; ++i) a += s_eq[i];
        out[32] = a * (1.f / 160.f);
    }
}

extern "C" void kernel_launch(void* const* d_in, const int* in_sizes, int n_in,
                              void* d_out, int out_size) {
    const float* xs  = (const float*)d_in[0];
    const int*   ysup= (const int*)  d_in[1];
    const float* xq  = (const float*)d_in[2];
    const int*   yqry= (const int*)  d_in[3];
    const float* k1 = (const float*)d_in[4];
    const float* b1 = (const float*)d_in[5];
    const float* g1 = (const float*)d_in[6];
    const float* be1= (const float*)d_in[7];
    const float* k2 = (const float*)d_in[8];
    const float* b2 = (const float*)d_in[9];
    const float* g2 = (const float*)d_in[10];
    const float* be2= (const float*)d_in[11];
    const float* k3 = (const float*)d_in[12];
    const float* b3 = (const float*)d_in[13];
    const float* g3 = (const float*)d_in[14];
    const float* be3= (const float*)d_in[15];
    const float* k4 = (const float*)d_in[16];
    const float* b4 = (const float*)d_in[17];
    const float* g4 = (const float*)d_in[18];
    const float* be4= (const float*)d_in[19];
    const float* fk = (const float*)d_in[20];
    const float* fr = (const float*)d_in[21];
    const float* fb = (const float*)d_in[22];
    const float* bk = (const float*)d_in[23];
    const float* br = (const float*)d_in[24];
    const float* bb = (const float*)d_in[25];
    float* out = (float*)d_out;

    float* cv; cudaGetSymbolAddress((void**)&cv, g_conv);
    float* p1; cudaGetSymbolAddress((void**)&p1, g_p1);
    float* p2; cudaGetSymbolAddress((void**)&p2, g_p2);
    float* p3; cudaGetSymbolAddress((void**)&p3, g_p3);
    float* em; cudaGetSymbolAddress((void**)&em, g_emb);

    // ---- layer 1: 84x84, 3->64 ----
    k_conv1<<<dim3(21, 800), 256>>>(xs, xq, k1, b1);
    k_stats<<<dim3(64, 25), 256>>>(cv, 84 * 84);
    k_sreduce<<<7, 256>>>();
    k_bnpool<<<(800*42*42*64 + 255) / 256, 256>>>(cv, p1, g1, be1, 84, 42,
                                                  1.f / (32.f * 7056.f), 800*42*42*64);
    // ---- layer 2: 42x42 (fp16x3 tensor core) ----
    k_wsplit_h<<<144, 256>>>(k2);
    k_conv64_mma<<<dim3(36, 800), 128>>>(p1, cv, b2, 42, 6);
    k_stats<<<dim3(64, 25), 256>>>(cv, 42 * 42);
    k_sreduce<<<7, 256>>>();
    k_bnpool<<<(800*21*21*64 + 255) / 256, 256>>>(cv, p2, g2, be2, 42, 21,
                                                  1.f / (32.f * 1764.f), 800*21*21*64);
    // ---- layer 3: 21x21 ----
    k_wsplit_h<<<144, 256>>>(k3);
    k_conv64_mma<<<dim3(9, 800), 128>>>(p2, cv, b3, 21, 3);
    k_stats<<<dim3(64, 25), 256>>>(cv, 21 * 21);
    k_sreduce<<<7, 256>>>();
    k_bnpool<<<(800*10*10*64 + 255) / 256, 256>>>(cv, p3, g3, be3, 21, 10,
                                                  1.f / (32.f * 441.f), 800*10*10*64);
    // ---- layer 4: 10x10 ----
    k_wsplit_h<<<144, 256>>>(k4);
    k_conv64_mma<<<dim3(4, 800), 128>>>(p3, cv, b4, 10, 2);
    k_stats<<<dim3(64, 25), 256>>>(cv, 10 * 10);
    k_sreduce<<<7, 256>>>();
    k_bnpool<<<(800*5*5*64 + 255) / 256, 256>>>(cv, em, g4, be4, 10, 5,
                                                1.f / (32.f * 100.f), 800*5*5*64);
    // ---- LSTM input GEMM, BiLSTM, epilogue ----
    k_xw<<<dim3(200, 2), 128>>>(fk, fb, bk, bb);
    k_lstm<<<dim3(5, 2), 128>>>(fr, br);
    k_final<<<1, 192>>>(ysup, yqry, out);
}